// round 9
// baseline (speedup 1.0000x reference)
#include <cuda_runtime.h>
#include <cuda_bf16.h>
#include <cstdint>

#define N_ROWS 8192
#define D_DIM  512
#define BM 128
#define BN 128
#define BK 64                   // bf16 elems per k-step (4 k16 substeps)
#define NKS (D_DIM / BK)        // 8 k-steps per tile
#define NB  (N_ROWS / BM)       // 64
#define NTILES (NB * (NB + 1) / 2)   // 2080
#define ROWB 128                // bytes per smem row (SW128 swizzled, no pad)
#define STAGES 3
#define STAGE_BYTES (256 * ROWB)             // 32768: A(128 rows)+B(128 rows)
#define SMEM_BYTES (STAGES * STAGE_BYTES)    // 98304 B

#define EXP10 22026.465794806718f
#define SCALE 14.426950408889634f   // (1/0.1)*log2(e), folded into g_fb

// ---- scratch ----
__device__ __nv_bfloat16 g_fa[N_ROWS * D_DIM];
__device__ __nv_bfloat16 g_fb[N_ROWS * D_DIM];
__device__ float g_pos[N_ROWS];
__device__ float g_tot[N_ROWS];
__device__ int   g_cl[N_ROWS];

// =============================== helpers ===================================
__device__ __forceinline__ uint32_t smem_u32(const void* p) {
    return (uint32_t)__cvta_generic_to_shared(p);
}
__device__ __forceinline__ void cp16(uint32_t saddr, const void* g) {
    asm volatile("cp.async.cg.shared.global [%0], [%1], 16;" :: "r"(saddr), "l"(g));
}
__device__ __forceinline__ void ldsm_x4(uint32_t addr, uint32_t* r) {
    asm volatile("ldmatrix.sync.aligned.m8n8.x4.shared.b16 {%0,%1,%2,%3},[%4];"
                 : "=r"(r[0]), "=r"(r[1]), "=r"(r[2]), "=r"(r[3]) : "r"(addr));
}
__device__ __forceinline__ void mma16816(float* c, const uint32_t* a,
                                         uint32_t b0, uint32_t b1) {
    asm volatile(
        "mma.sync.aligned.m16n8k16.row.col.f32.bf16.bf16.f32 "
        "{%0,%1,%2,%3},{%4,%5,%6,%7},{%8,%9},{%0,%1,%2,%3};"
        : "+f"(c[0]), "+f"(c[1]), "+f"(c[2]), "+f"(c[3])
        : "r"(a[0]), "r"(a[1]), "r"(a[2]), "r"(a[3]), "r"(b0), "r"(b1));
}
__device__ __forceinline__ float ex2(float x) {
    float e;
    asm("ex2.approx.f32 %0, %1;" : "=f"(e) : "f"(x));
    return e;
}

// =============================== small kernels ==============================
__global__ void init_kernel(const int* ca, float* out) {
    int i = blockIdx.x * blockDim.x + threadIdx.x;
    if (i == 0) out[0] = 0.0f;
    if (i >= N_ROWS) return;
    bool is64 = (ca[1] == 0) && (ca[3] == 0) && (ca[5] == 0) && (ca[7] == 0);
    g_cl[i]  = is64 ? ca[2 * i] : ca[i];
    g_pos[i] = 0.0f;
    g_tot[i] = 0.0f;
}

__global__ void norm_kernel(const float* __restrict__ f) {
    int row = blockIdx.x;
    const float* fr = f + (size_t)row * D_DIM;
    float v[4];
    float ss = 0.0f;
#pragma unroll
    for (int k = 0; k < 4; k++) { v[k] = fr[threadIdx.x + 128 * k]; ss += v[k] * v[k]; }
#pragma unroll
    for (int o = 16; o; o >>= 1) ss += __shfl_xor_sync(0xFFFFFFFFu, ss, o);
    __shared__ float s[4];
    if ((threadIdx.x & 31) == 0) s[threadIdx.x >> 5] = ss;
    __syncthreads();
    ss = s[0] + s[1] + s[2] + s[3];
    float r = 1.0f / fmaxf(sqrtf(ss), 1e-12f);
#pragma unroll
    for (int k = 0; k < 4; k++) {
        float x = v[k] * r;
        size_t idx = (size_t)row * D_DIM + threadIdx.x + 128 * k;
        g_fa[idx] = __float2bfloat16(x);
        g_fb[idx] = __float2bfloat16(x * SCALE);
    }
}

__global__ void dummy_kernel() {}   // ncu capture alignment (-s 5 lands on gemm)

__global__ void loss_kernel(float* __restrict__ out) {
    int i = blockIdx.x * blockDim.x + threadIdx.x;
    float sum = logf((g_tot[i] + 1e-8f) / g_pos[i]);
#pragma unroll
    for (int o = 16; o; o >>= 1) sum += __shfl_xor_sync(0xFFFFFFFFu, sum, o);
    __shared__ float s[8];
    if ((threadIdx.x & 31) == 0) s[threadIdx.x >> 5] = sum;
    __syncthreads();
    if (threadIdx.x < 32) {
        float v = (threadIdx.x < 8) ? s[threadIdx.x] : 0.0f;
#pragma unroll
        for (int o = 4; o; o >>= 1) v += __shfl_xor_sync(0xFFFFFFFFu, v, o);
        if (threadIdx.x == 0) atomicAdd(out, v);
    }
}

// =============================== main GEMM ==================================
// One 128x128 upper-triangular tile per CTA (2080 CTAs).
// 256 threads = 8 warps (4 M x 2 N), warp tile 32x64, bf16 HMMA.
// BK=64 stages in SW128 XOR-swizzled layout: conflict-free cp.async writes
// and ldsm reads; 8 barriers per tile instead of 16.
__global__ void __launch_bounds__(256, 2) gemm_hmma() {
    extern __shared__ char sm[];

    const int tid  = threadIdx.x;
    const int lane = tid & 31;
    const int w    = tid >> 5;
    const int wm   = w & 3;
    const int wn   = w >> 2;

    // ---- triangular tile map: t -> (bi, bj), bi <= bj ----
    const int t = blockIdx.x;
    int bi = (int)((129.0f - sqrtf(16641.0f - 8.0f * (float)t)) * 0.5f);
    while ((bi + 1) * NB - ((bi + 1) * bi) / 2 <= t) bi++;
    while (bi * NB - (bi * (bi - 1)) / 2 > t) bi--;
    const int bj = bi + (t - (bi * NB - (bi * (bi - 1)) / 2));
    const int i0 = bi * BM;
    const int j0 = bj * BN;
    const bool isdiag = (bi == bj);

    const uint32_t sm_base = smem_u32(sm);

    // ---- cp.async staging: thread -> one smem row (tid<128: A, else B) ----
    const __nv_bfloat16* grow = (tid < 128)
        ? g_fa + (size_t)(i0 + tid) * D_DIM
        : g_fb + (size_t)(j0 + tid - 128) * D_DIM;
    const uint32_t xorm = (uint32_t)((tid & 7) << 4);           // swizzle mask
    const uint32_t srow = sm_base + (uint32_t)(tid * ROWB);

    auto prefetch = [&](int g) {
        const uint32_t st = srow + (uint32_t)(g % STAGES) * STAGE_BYTES;
        const __nv_bfloat16* gp = grow + g * BK;
#pragma unroll
        for (int c = 0; c < 8; c++)
            cp16(st + ((uint32_t)(c << 4) ^ xorm), gp + c * 8);
        asm volatile("cp.async.commit_group;" ::: "memory");
    };

    // ---- ldsm base addresses (swizzle + lane chunk folded in via XOR) ----
    const int a_row = wm * 32 + (lane & 15);
    const uint32_t a_base = (sm_base + (uint32_t)(a_row * ROWB) +
                             (uint32_t)((a_row & 7) << 4)) ^
                            (uint32_t)((lane >> 4) << 4);
    const int b_row = wn * 64 + (lane & 7) + ((lane >> 4) << 3);
    const uint32_t b_base = (sm_base + (uint32_t)(128 * ROWB) +
                             (uint32_t)(b_row * ROWB) +
                             (uint32_t)((b_row & 7) << 4)) ^
                            (uint32_t)(((lane >> 3) & 1) << 4);

    float acc[2][8][4];
#pragma unroll
    for (int mi = 0; mi < 2; mi++)
#pragma unroll
        for (int ni = 0; ni < 8; ni++)
#pragma unroll
            for (int v = 0; v < 4; v++) acc[mi][ni][v] = 0.0f;

    prefetch(0);
    prefetch(1);

    for (int g = 0; g < NKS; g++) {
        asm volatile("cp.async.wait_group 1;" ::: "memory");
        __syncthreads();
        if (g + 2 < NKS) prefetch(g + 2);

        const uint32_t so = (uint32_t)(g % STAGES) * STAGE_BYTES;
        const uint32_t sa = a_base + so;
        const uint32_t sb = b_base + so;

#pragma unroll
        for (int s = 0; s < 4; s++) {            // k16 substeps within BK=64
            uint32_t a[2][4];
#pragma unroll
            for (int mi = 0; mi < 2; mi++)
                ldsm_x4((sa + (uint32_t)(mi * 16 * ROWB)) ^ (uint32_t)(s << 5),
                        a[mi]);
#pragma unroll
            for (int np = 0; np < 4; np++) {
                uint32_t b[4];
                ldsm_x4((sb + (uint32_t)(np * 16 * ROWB)) ^ (uint32_t)(s << 5), b);
#pragma unroll
                for (int mi = 0; mi < 2; mi++) {
                    mma16816(acc[mi][np * 2],     a[mi], b[0], b[1]);
                    mma16816(acc[mi][np * 2 + 1], a[mi], b[2], b[3]);
                }
            }
        }
    }

    // ---- epilogue: rows -> block bi, cols -> block bj (symmetric reuse) ----
    const int rbase = wm * 32 + (lane >> 2);
    int ci[4];
#pragma unroll
    for (int r = 0; r < 4; r++)
        ci[r] = g_cl[i0 + rbase + (r >> 1) * 16 + (r & 1) * 8];

    float tr[4] = {0, 0, 0, 0}, pr[4] = {0, 0, 0, 0};

#pragma unroll
    for (int ni = 0; ni < 8; ni++) {
        const int colb = wn * 64 + ni * 8 + (lane & 3) * 2;
        const int2 cjp = *(const int2*)&g_cl[j0 + colb];
        float ct[2] = {0, 0}, cp[2] = {0, 0};
#pragma unroll
        for (int mi = 0; mi < 2; mi++) {
#pragma unroll
            for (int v = 0; v < 4; v++) {
                const int h = v >> 1, vb = v & 1;
                const int ridx = mi * 2 + h;
                float e = ex2(acc[mi][ni][v]);
                if (isdiag && (rbase + mi * 16 + h * 8 == colb + vb)) e = EXP10;
                const bool m = (ci[ridx] == (vb ? cjp.y : cjp.x));
                tr[ridx] += e;
                if (m) pr[ridx] += e;
                ct[vb] += e;
                if (m) cp[vb] += e;
            }
        }
        if (!isdiag) {
#pragma unroll
            for (int o = 4; o <= 16; o <<= 1) {
#pragma unroll
                for (int vb = 0; vb < 2; vb++) {
                    ct[vb] += __shfl_xor_sync(0xFFFFFFFFu, ct[vb], o);
                    cp[vb] += __shfl_xor_sync(0xFFFFFFFFu, cp[vb], o);
                }
            }
            if (lane < 4) {
                atomicAdd(&g_tot[j0 + colb + 0], ct[0]);
                atomicAdd(&g_tot[j0 + colb + 1], ct[1]);
                atomicAdd(&g_pos[j0 + colb + 0], cp[0]);
                atomicAdd(&g_pos[j0 + colb + 1], cp[1]);
            }
        }
    }

#pragma unroll
    for (int r = 0; r < 4; r++) {
#pragma unroll
        for (int o = 1; o <= 2; o <<= 1) {
            tr[r] += __shfl_xor_sync(0xFFFFFFFFu, tr[r], o);
            pr[r] += __shfl_xor_sync(0xFFFFFFFFu, pr[r], o);
        }
    }
    if ((lane & 3) == 0) {
#pragma unroll
        for (int r = 0; r < 4; r++) {
            const int row = i0 + rbase + (r >> 1) * 16 + (r & 1) * 8;
            atomicAdd(&g_tot[row], tr[r]);
            atomicAdd(&g_pos[row], pr[r]);
        }
    }
}

// =============================== launch =====================================
extern "C" void kernel_launch(void* const* d_in, const int* in_sizes, int n_in,
                              void* d_out, int out_size) {
    const float* feat = (const float*)d_in[0];
    const int*   ca   = (const int*)d_in[1];

    static bool attr_done = false;
    if (!attr_done) {
        cudaFuncSetAttribute(gemm_hmma, cudaFuncAttributeMaxDynamicSharedMemorySize,
                             SMEM_BYTES);
        attr_done = true;
    }

    init_kernel<<<(N_ROWS + 255) / 256, 256>>>(ca, (float*)d_out);
    norm_kernel<<<N_ROWS, 128>>>(feat);
    dummy_kernel<<<1, 32>>>();
    gemm_hmma<<<NTILES, 256, SMEM_BYTES>>>();
    loss_kernel<<<N_ROWS / 256, 256>>>((float*)d_out);
}

// round 10
// speedup vs baseline: 1.3817x; 1.3817x over previous
#include <cuda_runtime.h>
#include <cuda_bf16.h>
#include <cstdint>

#define N_ROWS 8192
#define D_DIM  512
#define BM 128
#define BN 128
#define BK 32
#define NKS (D_DIM / BK)        // 16 k-steps per tile
#define NB  (N_ROWS / BM)       // 64
#define NTILES (NB * (NB + 1) / 2)   // 2080
#define LDS_STRIDE 40           // halves; 80B pitch, conflict-free for ldsm
#define STAGES 4
#define STAGE_HALVES (2 * BM * LDS_STRIDE)       // 10240 halves
#define SMEM_BYTES (STAGES * STAGE_HALVES * 2)   // 81920 B

#define EXP10 22026.465794806718f
#define SCALE 14.426950408889634f   // (1/0.1)*log2(e), folded into g_fb

// ---- scratch ----
__device__ __nv_bfloat16 g_fa[N_ROWS * D_DIM];
__device__ __nv_bfloat16 g_fb[N_ROWS * D_DIM];
__device__ float g_pos[N_ROWS];
__device__ float g_tot[N_ROWS];
__device__ int   g_cl[N_ROWS];

// =============================== helpers ===================================
__device__ __forceinline__ uint32_t smem_u32(const void* p) {
    return (uint32_t)__cvta_generic_to_shared(p);
}
__device__ __forceinline__ void cp16(uint32_t saddr, const void* g) {
    asm volatile("cp.async.cg.shared.global [%0], [%1], 16;" :: "r"(saddr), "l"(g));
}
__device__ __forceinline__ void ldsm_x4(uint32_t addr, uint32_t* r) {
    asm volatile("ldmatrix.sync.aligned.m8n8.x4.shared.b16 {%0,%1,%2,%3},[%4];"
                 : "=r"(r[0]), "=r"(r[1]), "=r"(r[2]), "=r"(r[3]) : "r"(addr));
}
__device__ __forceinline__ void mma16816(float* c, const uint32_t* a,
                                         uint32_t b0, uint32_t b1) {
    asm volatile(
        "mma.sync.aligned.m16n8k16.row.col.f32.bf16.bf16.f32 "
        "{%0,%1,%2,%3},{%4,%5,%6,%7},{%8,%9},{%0,%1,%2,%3};"
        : "+f"(c[0]), "+f"(c[1]), "+f"(c[2]), "+f"(c[3])
        : "r"(a[0]), "r"(a[1]), "r"(a[2]), "r"(a[3]), "r"(b0), "r"(b1));
}
__device__ __forceinline__ float ex2(float x) {
    float e;
    asm("ex2.approx.f32 %0, %1;" : "=f"(e) : "f"(x));
    return e;
}

// =============================== small kernels ==============================
__global__ void init_kernel(const int* ca, float* out) {
    int i = blockIdx.x * blockDim.x + threadIdx.x;
    if (i == 0) out[0] = 0.0f;
    if (i >= N_ROWS) return;
    bool is64 = (ca[1] == 0) && (ca[3] == 0) && (ca[5] == 0) && (ca[7] == 0);
    g_cl[i]  = is64 ? ca[2 * i] : ca[i];
    g_pos[i] = 0.0f;
    g_tot[i] = 0.0f;
}

__global__ void norm_kernel(const float* __restrict__ f) {
    int row = blockIdx.x;
    const float* fr = f + (size_t)row * D_DIM;
    float v[4];
    float ss = 0.0f;
#pragma unroll
    for (int k = 0; k < 4; k++) { v[k] = fr[threadIdx.x + 128 * k]; ss += v[k] * v[k]; }
#pragma unroll
    for (int o = 16; o; o >>= 1) ss += __shfl_xor_sync(0xFFFFFFFFu, ss, o);
    __shared__ float s[4];
    if ((threadIdx.x & 31) == 0) s[threadIdx.x >> 5] = ss;
    __syncthreads();
    ss = s[0] + s[1] + s[2] + s[3];
    float r = 1.0f / fmaxf(sqrtf(ss), 1e-12f);
#pragma unroll
    for (int k = 0; k < 4; k++) {
        float x = v[k] * r;
        size_t idx = (size_t)row * D_DIM + threadIdx.x + 128 * k;
        g_fa[idx] = __float2bfloat16(x);
        g_fb[idx] = __float2bfloat16(x * SCALE);
    }
}

__global__ void dummy_kernel() {}   // ncu capture alignment (-s 5 lands on gemm)

__global__ void loss_kernel(float* __restrict__ out) {
    int i = blockIdx.x * blockDim.x + threadIdx.x;
    float sum = logf((g_tot[i] + 1e-8f) / g_pos[i]);
#pragma unroll
    for (int o = 16; o; o >>= 1) sum += __shfl_xor_sync(0xFFFFFFFFu, sum, o);
    __shared__ float s[8];
    if ((threadIdx.x & 31) == 0) s[threadIdx.x >> 5] = sum;
    __syncthreads();
    if (threadIdx.x < 32) {
        float v = (threadIdx.x < 8) ? s[threadIdx.x] : 0.0f;
#pragma unroll
        for (int o = 4; o; o >>= 1) v += __shfl_xor_sync(0xFFFFFFFFu, v, o);
        if (threadIdx.x == 0) atomicAdd(out, v);
    }
}

// =============================== main GEMM ==================================
// One 128x128 upper-triangular tile per CTA (2080 CTAs).
// 256 threads = 8 warps (4 M x 2 N), warp tile 32x64, bf16 HMMA.
// Staging: lane l -> row w*8+(l&7), seg l>>3  => conflict-free smem writes
// (each 8-lane phase hits 8 distinct bank groups) with unchanged global
// coalescing (8 rows x 64B per warp instruction).
__global__ void __launch_bounds__(256, 2) gemm_hmma() {
    extern __shared__ __nv_bfloat16 sm[];

    const int tid  = threadIdx.x;
    const int lane = tid & 31;
    const int w    = tid >> 5;
    const int wm   = w & 3;
    const int wn   = w >> 2;

    // ---- triangular tile map: t -> (bi, bj), bi <= bj ----
    const int t = blockIdx.x;
    int bi = (int)((129.0f - sqrtf(16641.0f - 8.0f * (float)t)) * 0.5f);
    while ((bi + 1) * NB - ((bi + 1) * bi) / 2 <= t) bi++;
    while (bi * NB - (bi * (bi - 1)) / 2 > t) bi--;
    const int bj = bi + (t - (bi * NB - (bi * (bi - 1)) / 2));
    const int i0 = bi * BM;
    const int j0 = bj * BN;
    const bool isdiag = (bi == bj);

    // ---- cp.async staging (transposed lane assignment) ----
    const int srow = w * 8 + (lane & 7);        // 0..63
    const int seg  = lane >> 3;                 // 0..3
    const int gcol = seg * 8;                   // halves
    const uint32_t sm_base = smem_u32(sm);
    const uint32_t s_off0 = (uint32_t)((srow * LDS_STRIDE + gcol) * 2);
    const uint32_t s_off1 = (uint32_t)(((srow + 64) * LDS_STRIDE + gcol) * 2);
    const __nv_bfloat16* gA0 = g_fa + (size_t)(i0 + srow) * D_DIM + gcol;
    const __nv_bfloat16* gB0 = g_fb + (size_t)(j0 + srow) * D_DIM + gcol;

    auto prefetch = [&](int g) {
        const int kk = g << 5;
        const uint32_t st = (uint32_t)(g % STAGES) * (STAGE_HALVES * 2);
        cp16(sm_base + st + s_off0, gA0 + kk);
        cp16(sm_base + st + s_off1, gA0 + kk + 64 * D_DIM);
        const uint32_t bs = st + (uint32_t)(BM * LDS_STRIDE * 2);
        cp16(sm_base + bs + s_off0, gB0 + kk);
        cp16(sm_base + bs + s_off1, gB0 + kk + 64 * D_DIM);
        asm volatile("cp.async.commit_group;" ::: "memory");
    };

    // ---- ldsm geometry (unchanged from R5) ----
    const int a_row = wm * 32 + (lane & 15);
    const int a_col = (lane >> 4) << 3;
    const uint32_t a_off = (uint32_t)((a_row * LDS_STRIDE + a_col) * 2);
    const int b_row = wn * 64 + (lane & 7) + ((lane >> 4) << 3);
    const int b_col = ((lane >> 3) & 1) << 3;
    const uint32_t b_off = (uint32_t)((b_row * LDS_STRIDE + b_col) * 2) +
                           (uint32_t)(BM * LDS_STRIDE * 2);

    float acc[2][8][4];
#pragma unroll
    for (int mi = 0; mi < 2; mi++)
#pragma unroll
        for (int ni = 0; ni < 8; ni++)
#pragma unroll
            for (int v = 0; v < 4; v++) acc[mi][ni][v] = 0.0f;

    prefetch(0);
    prefetch(1);
    prefetch(2);

    uint32_t afr[2][2][4];
    uint32_t bfr[3][4];

    for (int g = 0; g < NKS; g++) {
        asm volatile("cp.async.wait_group 2;" ::: "memory");
        __syncthreads();
        if (g + 3 < NKS) prefetch(g + 3);

        const uint32_t stb = sm_base + (uint32_t)(g % STAGES) * (STAGE_HALVES * 2);
        const uint32_t sa = stb + a_off;
        const uint32_t sbb = stb + b_off;

        ldsm_x4(sa,                                        afr[0][0]);
        ldsm_x4(sa + (uint32_t)(16 * LDS_STRIDE * 2),      afr[0][1]);
        ldsm_x4(sa + 32,                                   afr[1][0]);
        ldsm_x4(sa + (uint32_t)(16 * LDS_STRIDE * 2) + 32, afr[1][1]);
        ldsm_x4(sbb, bfr[0]);

#pragma unroll
        for (int s = 0; s < 2; s++) {
#pragma unroll
            for (int np = 0; np < 4; np++) {
                const int it  = s * 4 + np;
                const int cur = it % 3;
                if (it + 1 < 8) {
                    const int nxt = (it + 1) % 3;
                    const int ns  = (np == 3) ? s + 1 : s;
                    const int nnp = (np + 1) & 3;
                    ldsm_x4(sbb + (uint32_t)(nnp * 16 * LDS_STRIDE * 2 + ns * 32),
                            bfr[nxt]);
                }
                mma16816(acc[0][np * 2],     afr[s][0], bfr[cur][0], bfr[cur][1]);
                mma16816(acc[0][np * 2 + 1], afr[s][0], bfr[cur][2], bfr[cur][3]);
                mma16816(acc[1][np * 2],     afr[s][1], bfr[cur][0], bfr[cur][1]);
                mma16816(acc[1][np * 2 + 1], afr[s][1], bfr[cur][2], bfr[cur][3]);
            }
        }
    }

    // ---- epilogue: rows -> block bi, cols -> block bj (symmetric reuse) ----
    const int rbase = wm * 32 + (lane >> 2);
    int ci[4];
#pragma unroll
    for (int r = 0; r < 4; r++)
        ci[r] = g_cl[i0 + rbase + (r >> 1) * 16 + (r & 1) * 8];

    float tr[4] = {0, 0, 0, 0}, pr[4] = {0, 0, 0, 0};

#pragma unroll
    for (int ni = 0; ni < 8; ni++) {
        const int colb = wn * 64 + ni * 8 + (lane & 3) * 2;
        const int2 cjp = *(const int2*)&g_cl[j0 + colb];
        float ct[2] = {0, 0}, cp[2] = {0, 0};
#pragma unroll
        for (int mi = 0; mi < 2; mi++) {
#pragma unroll
            for (int v = 0; v < 4; v++) {
                const int h = v >> 1, vb = v & 1;
                const int ridx = mi * 2 + h;
                float e = ex2(acc[mi][ni][v]);
                if (isdiag && (rbase + mi * 16 + h * 8 == colb + vb)) e = EXP10;
                const bool m = (ci[ridx] == (vb ? cjp.y : cjp.x));
                tr[ridx] += e;
                if (m) pr[ridx] += e;
                ct[vb] += e;
                if (m) cp[vb] += e;
            }
        }
        if (!isdiag) {
#pragma unroll
            for (int o = 4; o <= 16; o <<= 1) {
#pragma unroll
                for (int vb = 0; vb < 2; vb++) {
                    ct[vb] += __shfl_xor_sync(0xFFFFFFFFu, ct[vb], o);
                    cp[vb] += __shfl_xor_sync(0xFFFFFFFFu, cp[vb], o);
                }
            }
            if (lane < 4) {
                atomicAdd(&g_tot[j0 + colb + 0], ct[0]);
                atomicAdd(&g_tot[j0 + colb + 1], ct[1]);
                atomicAdd(&g_pos[j0 + colb + 0], cp[0]);
                atomicAdd(&g_pos[j0 + colb + 1], cp[1]);
            }
        }
    }

#pragma unroll
    for (int r = 0; r < 4; r++) {
#pragma unroll
        for (int o = 1; o <= 2; o <<= 1) {
            tr[r] += __shfl_xor_sync(0xFFFFFFFFu, tr[r], o);
            pr[r] += __shfl_xor_sync(0xFFFFFFFFu, pr[r], o);
        }
    }
    if ((lane & 3) == 0) {
#pragma unroll
        for (int r = 0; r < 4; r++) {
            const int row = i0 + rbase + (r >> 1) * 16 + (r & 1) * 8;
            atomicAdd(&g_tot[row], tr[r]);
            atomicAdd(&g_pos[row], pr[r]);
        }
    }
}

// =============================== launch =====================================
extern "C" void kernel_launch(void* const* d_in, const int* in_sizes, int n_in,
                              void* d_out, int out_size) {
    const float* feat = (const float*)d_in[0];
    const int*   ca   = (const int*)d_in[1];

    static bool attr_done = false;
    if (!attr_done) {
        cudaFuncSetAttribute(gemm_hmma, cudaFuncAttributeMaxDynamicSharedMemorySize,
                             SMEM_BYTES);
        attr_done = true;
    }

    init_kernel<<<(N_ROWS + 255) / 256, 256>>>(ca, (float*)d_out);
    norm_kernel<<<N_ROWS, 128>>>(feat);
    dummy_kernel<<<1, 32>>>();
    gemm_hmma<<<NTILES, 256, SMEM_BYTES>>>();
    loss_kernel<<<N_ROWS / 256, 256>>>((float*)d_out);
}

// round 11
// speedup vs baseline: 1.7482x; 1.2653x over previous
#include <cuda_runtime.h>
#include <cuda_bf16.h>
#include <cstdint>

#define N_ROWS 8192
#define D_DIM  512
#define BM 128
#define BN 128
#define BK 64                   // bf16 elems per k-step (4 k16 substeps)
#define NKS (D_DIM / BK)        // 8 k-steps per tile
#define NB  (N_ROWS / BM)       // 64
#define NTILES (NB * (NB + 1) / 2)   // 2080
#define ROWB 128                // bytes per smem row (SW128 swizzled)
#define STAGES 3
#define STAGE_BYTES (256 * ROWB)             // 32768: A(128 rows)+B(128 rows)
#define SMEM_BYTES (STAGES * STAGE_BYTES)    // 98304 B

#define EXP10 22026.465794806718f
#define SCALE 14.426950408889634f   // (1/0.1)*log2(e), folded into g_fb

// ---- scratch ----
__device__ __nv_bfloat16 g_fa[N_ROWS * D_DIM];
__device__ __nv_bfloat16 g_fb[N_ROWS * D_DIM];
__device__ float g_pos[N_ROWS];
__device__ float g_tot[N_ROWS];
__device__ int   g_cl[N_ROWS];

// =============================== helpers ===================================
__device__ __forceinline__ uint32_t smem_u32(const void* p) {
    return (uint32_t)__cvta_generic_to_shared(p);
}
__device__ __forceinline__ void cp16(uint32_t saddr, const void* g) {
    asm volatile("cp.async.cg.shared.global [%0], [%1], 16;" :: "r"(saddr), "l"(g));
}
__device__ __forceinline__ void ldsm_x4(uint32_t addr, uint32_t* r) {
    asm volatile("ldmatrix.sync.aligned.m8n8.x4.shared.b16 {%0,%1,%2,%3},[%4];"
                 : "=r"(r[0]), "=r"(r[1]), "=r"(r[2]), "=r"(r[3]) : "r"(addr));
}
__device__ __forceinline__ void mma16816(float* c, const uint32_t* a,
                                         uint32_t b0, uint32_t b1) {
    asm volatile(
        "mma.sync.aligned.m16n8k16.row.col.f32.bf16.bf16.f32 "
        "{%0,%1,%2,%3},{%4,%5,%6,%7},{%8,%9},{%0,%1,%2,%3};"
        : "+f"(c[0]), "+f"(c[1]), "+f"(c[2]), "+f"(c[3])
        : "r"(a[0]), "r"(a[1]), "r"(a[2]), "r"(a[3]), "r"(b0), "r"(b1));
}
__device__ __forceinline__ float ex2(float x) {
    float e;
    asm("ex2.approx.f32 %0, %1;" : "=f"(e) : "f"(x));
    return e;
}

// =============================== small kernels ==============================
__global__ void init_kernel(const int* ca, float* out) {
    int i = blockIdx.x * blockDim.x + threadIdx.x;
    if (i == 0) out[0] = 0.0f;
    if (i >= N_ROWS) return;
    bool is64 = (ca[1] == 0) && (ca[3] == 0) && (ca[5] == 0) && (ca[7] == 0);
    g_cl[i]  = is64 ? ca[2 * i] : ca[i];
    g_pos[i] = 0.0f;
    g_tot[i] = 0.0f;
}

__global__ void norm_kernel(const float* __restrict__ f) {
    int row = blockIdx.x;
    const float* fr = f + (size_t)row * D_DIM;
    float v[4];
    float ss = 0.0f;
#pragma unroll
    for (int k = 0; k < 4; k++) { v[k] = fr[threadIdx.x + 128 * k]; ss += v[k] * v[k]; }
#pragma unroll
    for (int o = 16; o; o >>= 1) ss += __shfl_xor_sync(0xFFFFFFFFu, ss, o);
    __shared__ float s[4];
    if ((threadIdx.x & 31) == 0) s[threadIdx.x >> 5] = ss;
    __syncthreads();
    ss = s[0] + s[1] + s[2] + s[3];
    float r = 1.0f / fmaxf(sqrtf(ss), 1e-12f);
#pragma unroll
    for (int k = 0; k < 4; k++) {
        float x = v[k] * r;
        size_t idx = (size_t)row * D_DIM + threadIdx.x + 128 * k;
        g_fa[idx] = __float2bfloat16(x);
        g_fb[idx] = __float2bfloat16(x * SCALE);
    }
}

__global__ void dummy_kernel() {}   // ncu capture alignment (-s 5 lands on gemm)

__global__ void loss_kernel(float* __restrict__ out) {
    int i = blockIdx.x * blockDim.x + threadIdx.x;
    float sum = logf((g_tot[i] + 1e-8f) / g_pos[i]);
#pragma unroll
    for (int o = 16; o; o >>= 1) sum += __shfl_xor_sync(0xFFFFFFFFu, sum, o);
    __shared__ float s[8];
    if ((threadIdx.x & 31) == 0) s[threadIdx.x >> 5] = sum;
    __syncthreads();
    if (threadIdx.x < 32) {
        float v = (threadIdx.x < 8) ? s[threadIdx.x] : 0.0f;
#pragma unroll
        for (int o = 4; o; o >>= 1) v += __shfl_xor_sync(0xFFFFFFFFu, v, o);
        if (threadIdx.x == 0) atomicAdd(out, v);
    }
}

// =============================== main GEMM ==================================
// One 128x128 upper-triangular tile per CTA (2080 CTAs).
// 256 threads = 8 warps (4 M x 2 N), warp tile 32x64, bf16 HMMA.
// SW128 swizzled BK=64 stages. Staging: lane l -> chunk l&7, row tid>>3 (+32q):
// per warp instruction = 4 full 128B lines (coalesced) AND conflict-free
// swizzled smem writes. ldsm addressing identical to R9 (validated).
__global__ void __launch_bounds__(256, 2) gemm_hmma() {
    extern __shared__ char sm[];

    const int tid  = threadIdx.x;
    const int lane = tid & 31;
    const int w    = tid >> 5;
    const int wm   = w & 3;
    const int wn   = w >> 2;

    // ---- triangular tile map: t -> (bi, bj), bi <= bj ----
    const int t = blockIdx.x;
    int bi = (int)((129.0f - sqrtf(16641.0f - 8.0f * (float)t)) * 0.5f);
    while ((bi + 1) * NB - ((bi + 1) * bi) / 2 <= t) bi++;
    while (bi * NB - (bi * (bi - 1)) / 2 > t) bi--;
    const int bj = bi + (t - (bi * NB - (bi * (bi - 1)) / 2));
    const int i0 = bi * BM;
    const int j0 = bj * BN;
    const bool isdiag = (bi == bj);

    const uint32_t sm_base = smem_u32(sm);

    // ---- staging geometry: chunk-per-lane, coalesced + conflict-free ----
    const int c  = lane & 7;            // 16B chunk within 128B row
    const int r0 = tid >> 3;            // base row 0..31 (A); +32q covers all
    const uint32_t sw0 = (uint32_t)(r0 * ROWB) +
                         (uint32_t)(((c ^ (r0 & 7)) & 7) << 4);
    const __nv_bfloat16* gA = g_fa + (size_t)(i0 + r0) * D_DIM + c * 8;
    const __nv_bfloat16* gB = g_fb + (size_t)(j0 + r0) * D_DIM + c * 8;

    auto prefetch = [&](int g) {
        const uint32_t st = sm_base + (uint32_t)(g % STAGES) * STAGE_BYTES + sw0;
        const __nv_bfloat16* ga = gA + g * BK;
        const __nv_bfloat16* gb = gB + g * BK;
#pragma unroll
        for (int q = 0; q < 4; q++) {
            cp16(st + q * (32 * ROWB), ga + q * 32 * D_DIM);
            cp16(st + 128 * ROWB + q * (32 * ROWB), gb + q * 32 * D_DIM);
        }
        asm volatile("cp.async.commit_group;" ::: "memory");
    };

    // ---- ldsm base addresses (identical to R9, validated) ----
    const int a_row = wm * 32 + (lane & 15);
    const uint32_t a_base = (sm_base + (uint32_t)(a_row * ROWB) +
                             (uint32_t)((a_row & 7) << 4)) ^
                            (uint32_t)((lane >> 4) << 4);
    const int b_row = wn * 64 + (lane & 7) + ((lane >> 4) << 3);
    const uint32_t b_base = (sm_base + (uint32_t)(128 * ROWB) +
                             (uint32_t)(b_row * ROWB) +
                             (uint32_t)((b_row & 7) << 4)) ^
                            (uint32_t)(((lane >> 3) & 1) << 4);

    float acc[2][8][4];
#pragma unroll
    for (int mi = 0; mi < 2; mi++)
#pragma unroll
        for (int ni = 0; ni < 8; ni++)
#pragma unroll
            for (int v = 0; v < 4; v++) acc[mi][ni][v] = 0.0f;

    prefetch(0);
    prefetch(1);

    for (int g = 0; g < NKS; g++) {
        asm volatile("cp.async.wait_group 1;" ::: "memory");
        __syncthreads();
        if (g + 2 < NKS) prefetch(g + 2);

        const uint32_t so = (uint32_t)(g % STAGES) * STAGE_BYTES;
        const uint32_t sa = a_base + so;
        const uint32_t sb = b_base + so;

#pragma unroll
        for (int s = 0; s < 4; s++) {            // k16 substeps within BK=64
            uint32_t a[2][4];
#pragma unroll
            for (int mi = 0; mi < 2; mi++)
                ldsm_x4((sa + (uint32_t)(mi * 16 * ROWB)) ^ (uint32_t)(s << 5),
                        a[mi]);
#pragma unroll
            for (int np = 0; np < 4; np++) {
                uint32_t b[4];
                ldsm_x4((sb + (uint32_t)(np * 16 * ROWB)) ^ (uint32_t)(s << 5), b);
#pragma unroll
                for (int mi = 0; mi < 2; mi++) {
                    mma16816(acc[mi][np * 2],     a[mi], b[0], b[1]);
                    mma16816(acc[mi][np * 2 + 1], a[mi], b[2], b[3]);
                }
            }
        }
    }

    // ---- epilogue: rows -> block bi, cols -> block bj (symmetric reuse) ----
    const int rbase = wm * 32 + (lane >> 2);
    int ci[4];
#pragma unroll
    for (int r = 0; r < 4; r++)
        ci[r] = g_cl[i0 + rbase + (r >> 1) * 16 + (r & 1) * 8];

    float tr[4] = {0, 0, 0, 0}, pr[4] = {0, 0, 0, 0};

#pragma unroll
    for (int ni = 0; ni < 8; ni++) {
        const int colb = wn * 64 + ni * 8 + (lane & 3) * 2;
        const int2 cjp = *(const int2*)&g_cl[j0 + colb];
        float ct[2] = {0, 0}, cp[2] = {0, 0};
#pragma unroll
        for (int mi = 0; mi < 2; mi++) {
#pragma unroll
            for (int v = 0; v < 4; v++) {
                const int h = v >> 1, vb = v & 1;
                const int ridx = mi * 2 + h;
                float e = ex2(acc[mi][ni][v]);
                if (isdiag && (rbase + mi * 16 + h * 8 == colb + vb)) e = EXP10;
                const bool m = (ci[ridx] == (vb ? cjp.y : cjp.x));
                tr[ridx] += e;
                if (m) pr[ridx] += e;
                ct[vb] += e;
                if (m) cp[vb] += e;
            }
        }
        if (!isdiag) {
#pragma unroll
            for (int o = 4; o <= 16; o <<= 1) {
#pragma unroll
                for (int vb = 0; vb < 2; vb++) {
                    ct[vb] += __shfl_xor_sync(0xFFFFFFFFu, ct[vb], o);
                    cp[vb] += __shfl_xor_sync(0xFFFFFFFFu, cp[vb], o);
                }
            }
            if (lane < 4) {
                atomicAdd(&g_tot[j0 + colb + 0], ct[0]);
                atomicAdd(&g_tot[j0 + colb + 1], ct[1]);
                atomicAdd(&g_pos[j0 + colb + 0], cp[0]);
                atomicAdd(&g_pos[j0 + colb + 1], cp[1]);
            }
        }
    }

#pragma unroll
    for (int r = 0; r < 4; r++) {
#pragma unroll
        for (int o = 1; o <= 2; o <<= 1) {
            tr[r] += __shfl_xor_sync(0xFFFFFFFFu, tr[r], o);
            pr[r] += __shfl_xor_sync(0xFFFFFFFFu, pr[r], o);
        }
    }
    if ((lane & 3) == 0) {
#pragma unroll
        for (int r = 0; r < 4; r++) {
            const int row = i0 + rbase + (r >> 1) * 16 + (r & 1) * 8;
            atomicAdd(&g_tot[row], tr[r]);
            atomicAdd(&g_pos[row], pr[r]);
        }
    }
}

// =============================== launch =====================================
extern "C" void kernel_launch(void* const* d_in, const int* in_sizes, int n_in,
                              void* d_out, int out_size) {
    const float* feat = (const float*)d_in[0];
    const int*   ca   = (const int*)d_in[1];

    static bool attr_done = false;
    if (!attr_done) {
        cudaFuncSetAttribute(gemm_hmma, cudaFuncAttributeMaxDynamicSharedMemorySize,
                             SMEM_BYTES);
        attr_done = true;
    }

    init_kernel<<<(N_ROWS + 255) / 256, 256>>>(ca, (float*)d_out);
    norm_kernel<<<N_ROWS, 128>>>(feat);
    dummy_kernel<<<1, 32>>>();
    gemm_hmma<<<NTILES, 256, SMEM_BYTES>>>();
    loss_kernel<<<N_ROWS / 256, 256>>>((float*)d_out);
}